// round 11
// baseline (speedup 1.0000x reference)
#include <cuda_runtime.h>
#include <cuda_fp16.h>
#include <cstdint>
#include <math.h>

// ---------------- problem dims ----------------
#define T_TOK   16384
#define DDIM    1024
#define HDIM    4096
#define NEXP    8
#define NASSIGN (T_TOK * 2)
#define TILE_M  128
#define TILE_N  128
#define BK      64
#define STG     4
#define MAX_T2  (NASSIGN / TILE_M + NEXP)   // 264

// ---------------- static device scratch ----------------
__device__ __half g_xh [(size_t)T_TOK * DDIM];
__device__ __half g_w1t[(size_t)NEXP * HDIM * DDIM];   // [E][H][D]  ([N][K] K-major)
__device__ __half g_w2t[(size_t)NEXP * DDIM * HDIM];   // [E][D][H]  ([N][K] K-major)
__device__ __half g_hbuf[(size_t)NASSIGN * HDIM];
__device__ float  g_y  [(size_t)NASSIGN * DDIM];

__device__ int   g_cnt[NEXP];
__device__ int   g_fill[NEXP];
__device__ int   g_off[NEXP];
__device__ int   g_tok_e[T_TOK * 2];
__device__ float g_tok_w[T_TOK * 2];
__device__ int   g_rows[NASSIGN];
__device__ int   g_slot_of[T_TOK * 2];
__device__ int   g_tile_e[MAX_T2 + 8];
__device__ int   g_tile_r[MAX_T2 + 8];
__device__ int   g_nt;

// ---------------- PTX helpers (base-target only: sm_80-class) ----------------
__device__ __forceinline__ uint32_t smem_u32(const void* p) {
    uint32_t a;
    asm("{ .reg .u64 t; cvta.to.shared.u64 t, %1; cvt.u32.u64 %0, t; }" : "=r"(a) : "l"(p));
    return a;
}
__device__ __forceinline__ void cp16s(uint32_t s, const void* g, bool v) {
    int sz = v ? 16 : 0;
    asm volatile("cp.async.cg.shared.global [%0], [%1], 16, %2;\n" :: "r"(s), "l"(g), "r"(sz) : "memory");
}
__device__ __forceinline__ void cp_commit() { asm volatile("cp.async.commit_group;\n" ::: "memory"); }
__device__ __forceinline__ void cp_wait2()  { asm volatile("cp.async.wait_group 2;\n" ::: "memory"); }

__device__ __forceinline__ void ldsm4(uint32_t* r, uint32_t addr) {
    asm volatile("ldmatrix.sync.aligned.m8n8.x4.shared.b16 {%0,%1,%2,%3}, [%4];"
                 : "=r"(r[0]), "=r"(r[1]), "=r"(r[2]), "=r"(r[3]) : "r"(addr));
}
__device__ __forceinline__ void mma16816(float* c, const uint32_t* a, uint32_t b0, uint32_t b1) {
    asm volatile("mma.sync.aligned.m16n8k16.row.col.f32.f16.f16.f32 "
                 "{%0,%1,%2,%3}, {%4,%5,%6,%7}, {%8,%9}, {%0,%1,%2,%3};"
                 : "+f"(c[0]), "+f"(c[1]), "+f"(c[2]), "+f"(c[3])
                 : "r"(a[0]), "r"(a[1]), "r"(a[2]), "r"(a[3]), "r"(b0), "r"(b1));
}

#define SWZ(o) ((o) ^ (((o) >> 3) & 0x70))

// fast gelu (tanh form) on 2 values, fp16x2 SIMD + MUFU.TANH
__device__ __forceinline__ __half2 gelu2(float x0, float x1) {
    __half2 x = __floats2half2_rn(x0, x1);
    __half2 u = __hmul2(x, x);
    __half2 v = __hfma2(u, __float2half2_rn(0.044715f), __float2half2_rn(1.0f));
    __half2 w = __hmul2(__hmul2(x, v), __float2half2_rn(0.79788456f));
    uint32_t wi = *(uint32_t*)&w, ti;
    asm("tanh.approx.f16x2 %0, %1;" : "=r"(ti) : "r"(wi));
    __half2 th = *(__half2*)&ti;
    return __hmul2(__hmul2(x, __float2half2_rn(0.5f)), __hadd2(th, __float2half2_rn(1.0f)));
}

// ---------------- prep kernels ----------------
__global__ void tr_f2h_kernel(const float* __restrict__ in, __half* __restrict__ out, int R, int C) {
    __shared__ float t[32][33];
    int e = blockIdx.z;
    const float* ie = in + (size_t)e * R * C;
    __half* oe = out + (size_t)e * R * C;
    int c0 = blockIdx.x * 32, r0 = blockIdx.y * 32;
    int tx = threadIdx.x, ty = threadIdx.y;
#pragma unroll
    for (int k = 0; k < 32; k += 8)
        t[ty + k][tx] = ie[(size_t)(r0 + ty + k) * C + c0 + tx];
    __syncthreads();
#pragma unroll
    for (int k = 0; k < 32; k += 8)
        oe[(size_t)(c0 + ty + k) * R + r0 + tx] = __float2half(t[tx][ty + k]);
}

__global__ void f2h_x_kernel(const float4* __restrict__ in, __half2* __restrict__ out, int n4) {
    if (blockIdx.x == 0 && threadIdx.x < NEXP) { g_cnt[threadIdx.x] = 0; g_fill[threadIdx.x] = 0; }
    int i = blockIdx.x * blockDim.x + threadIdx.x;
    if (i < n4) {
        float4 v = in[i];
        out[2 * i]     = __floats2half2_rn(v.x, v.y);
        out[2 * i + 1] = __floats2half2_rn(v.z, v.w);
    }
}

// ---------------- router ----------------
__global__ void router_kernel(const float* __restrict__ x,
                              const float* __restrict__ rw,
                              float* __restrict__ logits_out) {
    int gwarp = (blockIdx.x * blockDim.x + threadIdx.x) >> 5;
    int lane  = threadIdx.x & 31;
    if (gwarp >= T_TOK) return;
    const float* xr = x + (size_t)gwarp * DDIM;
    float acc[NEXP];
#pragma unroll
    for (int e = 0; e < NEXP; e++) acc[e] = 0.f;
    for (int d = lane; d < DDIM; d += 32) {
        float xv = xr[d];
        const float* r = rw + d * NEXP;
#pragma unroll
        for (int e = 0; e < NEXP; e++) acc[e] += xv * r[e];
    }
#pragma unroll
    for (int e = 0; e < NEXP; e++)
#pragma unroll
        for (int o = 16; o > 0; o >>= 1)
            acc[e] += __shfl_xor_sync(0xffffffffu, acc[e], o);
    if (lane == 0) {
#pragma unroll
        for (int e = 0; e < NEXP; e++) logits_out[(size_t)gwarp * NEXP + e] = acc[e];
        float m = acc[0];
#pragma unroll
        for (int e = 1; e < NEXP; e++) m = fmaxf(m, acc[e]);
        float p[NEXP]; float s = 0.f;
#pragma unroll
        for (int e = 0; e < NEXP; e++) { p[e] = expf(acc[e] - m); s += p[e]; }
        float inv = 1.f / s;
        int e0 = 0; float p0 = p[0];
#pragma unroll
        for (int e = 1; e < NEXP; e++) if (p[e] > p0) { p0 = p[e]; e0 = e; }
        int e1 = -1; float p1 = -1.f;
#pragma unroll
        for (int e = 0; e < NEXP; e++)
            if (e != e0 && p[e] > p1) { p1 = p[e]; e1 = e; }
        g_tok_e[2 * gwarp]     = e0;
        g_tok_e[2 * gwarp + 1] = e1;
        g_tok_w[2 * gwarp]     = p0 * inv;
        g_tok_w[2 * gwarp + 1] = p1 * inv;
        atomicAdd(&g_cnt[e0], 1);
        atomicAdd(&g_cnt[e1], 1);
    }
}

// ---------------- scan + compact assignment ----------------
__global__ void scan_assign_kernel() {
    if (threadIdx.x == 0) {
        int off = 0, nt = 0;
        for (int e = 0; e < NEXP; e++) {
            g_off[e] = off;
            int c = g_cnt[e];
            off += c;
            int t = (c + TILE_M - 1) / TILE_M;
            for (int i = 0; i < t; i++) { g_tile_e[nt] = e; g_tile_r[nt] = i * TILE_M; nt++; }
        }
        g_nt = nt;
    }
    __syncthreads();
    for (int t = threadIdx.x; t < T_TOK; t += blockDim.x) {
#pragma unroll
        for (int k = 0; k < 2; k++) {
            int e = g_tok_e[2 * t + k];
            int p = atomicAdd(&g_fill[e], 1);
            int s = g_off[e] + p;
            g_rows[s] = t;
            g_slot_of[2 * t + k] = s;
        }
    }
}

// ---------------- mma.sync grouped GEMM ----------------
// CTA 128x128, BK=64, 4-stage cp.async, 8 warps (2x4), warp tile 64x32.
// A rows: 128B (64 halfs) SW128-swizzled; B [N][K] rows likewise.
// MODE 0: A gathered via g_rows; epilogue fast-gelu -> g_hbuf (fp16)
// MODE 1: A = g_hbuf slots; epilogue +bias -> g_y (fp32)
#define ASTG (TILE_M * 128)     // 16384 B per stage
#define BSTG (TILE_N * 128)
#define SMEM_DYN (1024 + STG * (ASTG + BSTG))

template <int MODE>
__global__ void __launch_bounds__(256, 1)
gemm_mma(const __half* __restrict__ Ab, const __half* __restrict__ Bb,
         const float* __restrict__ bv, int K, int Nfull) {
    extern __shared__ char smem_raw[];
    int tile = blockIdx.x;
    if (tile >= g_nt) return;
    uint32_t sbase = (smem_u32(smem_raw) + 1023u) & ~1023u;
    const uint32_t sA = sbase;
    const uint32_t sB = sbase + STG * ASTG;

    int e     = g_tile_e[tile];
    int r0    = g_tile_r[tile];
    int slot0 = g_off[e] + r0;
    int rows  = g_cnt[e] - r0; if (rows > TILE_M) rows = TILE_M;
    int n0    = blockIdx.y * TILE_N;

    int tid  = threadIdx.x;
    int wid  = tid >> 5;
    int lane = tid & 31;
    int wm   = wid >> 2;     // 0..1
    int wn   = wid & 3;      // 0..3

    // ---- load mapping: tid<128 -> A row tid; tid>=128 -> B row tid-128 ----
    int lrow = (tid < 128) ? tid : (tid - 128);
    const __half* gp;
    if (tid < 128) {
        long ar;
        if (MODE == 0) ar = (lrow < rows) ? g_rows[slot0 + lrow] : 0;
        else           ar = (slot0 + lrow < NASSIGN) ? (slot0 + lrow) : 0;
        gp = Ab + (size_t)ar * K;
    } else {
        gp = Bb + ((size_t)e * Nfull + n0 + lrow) * K;
    }
    uint32_t sdst = (tid < 128) ? sA : sB;
    uint32_t swo[8];
#pragma unroll
    for (int j = 0; j < 8; j++) swo[j] = SWZ(lrow * 128 + j * 16);

    auto load_stage = [&](int st, int k0) {
        uint32_t base = sdst + st * ((tid < 128) ? ASTG : BSTG);
#pragma unroll
        for (int j = 0; j < 8; j++) cp16s(base + swo[j], gp + k0 + j * 8, true);
        cp_commit();
    };

    float acc[4][4][4];
#pragma unroll
    for (int mi = 0; mi < 4; mi++)
#pragma unroll
        for (int ni = 0; ni < 4; ni++)
#pragma unroll
            for (int q = 0; q < 4; q++) acc[mi][ni][q] = 0.f;

    const int nk = K / BK;
    load_stage(0, 0);
    load_stage(1, BK);
    load_stage(2, 2 * BK);

    // precomputed ldmatrix address components
    int lr16 = lane & 15;
    int lhi  = (lane >> 4) & 1;

    for (int kt = 0; kt < nk; kt++) {
        cp_wait2();
        __syncthreads();
        if (kt + 3 < nk) load_stage((kt + 3) & 3, (kt + 3) * BK);
        else             cp_commit();   // keep group count invariant

        uint32_t sa = sA + (kt & 3) * ASTG;
        uint32_t sb = sB + (kt & 3) * BSTG;
#pragma unroll
        for (int kk = 0; kk < 4; kk++) {
            uint32_t a[4][4], b[2][4];
#pragma unroll
            for (int mi = 0; mi < 4; mi++) {
                int row = wm * 64 + mi * 16 + lr16;
                ldsm4(a[mi], sa + SWZ(row * 128 + kk * 32 + lhi * 16));
            }
#pragma unroll
            for (int nb = 0; nb < 2; nb++) {
                int nrow = wn * 32 + nb * 16 + lr16;
                ldsm4(b[nb], sb + SWZ(nrow * 128 + kk * 32 + lhi * 16));
            }
#pragma unroll
            for (int mi = 0; mi < 4; mi++) {
#pragma unroll
                for (int nb = 0; nb < 2; nb++) {
                    mma16816(acc[mi][2 * nb],     a[mi], b[nb][0], b[nb][2]);
                    mma16816(acc[mi][2 * nb + 1], a[mi], b[nb][1], b[nb][3]);
                }
            }
        }
    }

    // ---- epilogue: direct from fragments ----
    int g  = lane >> 2;
    int cc = (lane & 3) * 2;
    const float* bvr = bv + (size_t)e * Nfull + n0 + wn * 32;
#pragma unroll
    for (int mi = 0; mi < 4; mi++) {
        int rA = wm * 64 + mi * 16 + g;
        int rB = rA + 8;
#pragma unroll
        for (int ni = 0; ni < 4; ni++) {
            int col = ni * 8 + cc;
            float b0 = bvr[col], b1 = bvr[col + 1];
            if (MODE == 0) {
                if (rA < rows) {
                    __half2 h = gelu2(acc[mi][ni][0] + b0, acc[mi][ni][1] + b1);
                    *(__half2*)(g_hbuf + (size_t)(slot0 + rA) * HDIM + n0 + wn * 32 + col) = h;
                }
                if (rB < rows) {
                    __half2 h = gelu2(acc[mi][ni][2] + b0, acc[mi][ni][3] + b1);
                    *(__half2*)(g_hbuf + (size_t)(slot0 + rB) * HDIM + n0 + wn * 32 + col) = h;
                }
            } else {
                if (rA < rows) {
                    float2 o; o.x = acc[mi][ni][0] + b0; o.y = acc[mi][ni][1] + b1;
                    *(float2*)(g_y + (size_t)(slot0 + rA) * DDIM + n0 + wn * 32 + col) = o;
                }
                if (rB < rows) {
                    float2 o; o.x = acc[mi][ni][2] + b0; o.y = acc[mi][ni][3] + b1;
                    *(float2*)(g_y + (size_t)(slot0 + rB) * DDIM + n0 + wn * 32 + col) = o;
                }
            }
        }
    }
}

// ---------------- combine ----------------
__global__ void combine_kernel(const float* __restrict__ bias, float* __restrict__ out) {
    int i = blockIdx.x * blockDim.x + threadIdx.x;
    if (i >= T_TOK * (DDIM / 4)) return;
    int t = i >> 8;
    int c = (i & 255) << 2;
    float w0 = g_tok_w[2 * t];
    float w1 = g_tok_w[2 * t + 1];
    int   s0 = g_slot_of[2 * t];
    int   s1 = g_slot_of[2 * t + 1];
    float4 y0 = *(const float4*)&g_y[(size_t)s0 * DDIM + c];
    float4 y1 = *(const float4*)&g_y[(size_t)s1 * DDIM + c];
    float4 bv = *(const float4*)&bias[c];
    float4 o;
    o.x = bv.x + w0 * y0.x + w1 * y1.x;
    o.y = bv.y + w0 * y0.y + w1 * y1.y;
    o.z = bv.z + w0 * y0.z + w1 * y1.z;
    o.w = bv.w + w0 * y0.w + w1 * y1.w;
    *(float4*)&out[(size_t)t * DDIM + c] = o;
}

// ---------------- launch ----------------
extern "C" void kernel_launch(void* const* d_in, const int* in_sizes, int n_in,
                              void* d_out, int out_size) {
    const float* x    = (const float*)d_in[0];
    const float* rw   = (const float*)d_in[1];
    const float* w1   = (const float*)d_in[2];
    const float* b1   = (const float*)d_in[3];
    const float* w2   = (const float*)d_in[4];
    const float* b2   = (const float*)d_in[5];
    const float* bias = (const float*)d_in[6];
    float* out    = (float*)d_out;
    float* logits = out + (size_t)T_TOK * DDIM;

    void *p_xh, *p_w1t, *p_w2t, *p_hbuf;
    cudaGetSymbolAddress(&p_xh,   g_xh);
    cudaGetSymbolAddress(&p_w1t,  g_w1t);
    cudaGetSymbolAddress(&p_w2t,  g_w2t);
    cudaGetSymbolAddress(&p_hbuf, g_hbuf);

    cudaFuncSetAttribute(gemm_mma<0>, cudaFuncAttributeMaxDynamicSharedMemorySize, SMEM_DYN);
    cudaFuncSetAttribute(gemm_mma<1>, cudaFuncAttributeMaxDynamicSharedMemorySize, SMEM_DYN);

    // 1-2: weight transposes (fp32 -> fp16, [E][K][N] -> [E][N][K])
    tr_f2h_kernel<<<dim3(HDIM / 32, DDIM / 32, NEXP), dim3(32, 8)>>>(w1, (__half*)p_w1t, DDIM, HDIM);
    tr_f2h_kernel<<<dim3(DDIM / 32, HDIM / 32, NEXP), dim3(32, 8)>>>(w2, (__half*)p_w2t, HDIM, DDIM);
    // 3: x conversion (+ counter zeroing)
    {
        int n4 = (T_TOK * DDIM) / 4;
        f2h_x_kernel<<<(n4 + 255) / 256, 256>>>((const float4*)x, (__half2*)p_xh, n4);
    }
    // 4: router
    router_kernel<<<T_TOK / 8, 256>>>(x, rw, logits);
    // 5: scan + compact assignment
    scan_assign_kernel<<<1, 1024>>>();
    // 6: GEMM1 (captured by ncu -s 5 -c 1)
    gemm_mma<0><<<dim3(MAX_T2, HDIM / TILE_N), 256, SMEM_DYN>>>(
        (const __half*)p_xh, (const __half*)p_w1t, b1, DDIM, HDIM);
    // 7: GEMM2
    gemm_mma<1><<<dim3(MAX_T2, DDIM / TILE_N), 256, SMEM_DYN>>>(
        (const __half*)p_hbuf, (const __half*)p_w2t, b2, HDIM, DDIM);
    // 8: combine
    combine_kernel<<<(T_TOK * (DDIM / 4) + 255) / 256, 256>>>(bias, out);
}